// round 16
// baseline (speedup 1.0000x reference)
#include <cuda_runtime.h>
#include <cuda_bf16.h>
#include <cstdint>

#define BATCH 32
#define NTOK  1024
#define DIM   256
#define KNN   8
#define NCAND 16
#define EPSV  1e-8f

typedef unsigned long long u64;

// ---- scratch (static __device__ globals; no allocation allowed) ----
__device__ float         g_tn [(size_t)BATCH * NTOK * DIM];   // 32 MB fp32 (exact rescore)
__device__ __nv_bfloat16 g_tnh[(size_t)BATCH * NTOK * DIM];   // 16 MB bf16 (MMA filter)
__device__ float         g_sim[(size_t)BATCH * NTOK * NTOK];  // 134 MB approx sim
__device__ int           g_cand[BATCH * NTOK * NCAND];        // 2 MB candidates
__device__ int           g_topk[BATCH * NTOK * KNN];          // 1 MB exact top-8

__device__ __forceinline__ void ldsm_x4(uint32_t& r0, uint32_t& r1,
                                        uint32_t& r2, uint32_t& r3,
                                        const void* p) {
    uint32_t addr = (uint32_t)__cvta_generic_to_shared(p);
    asm volatile("ldmatrix.sync.aligned.m8n8.x4.shared.b16 {%0,%1,%2,%3}, [%4];"
                 : "=r"(r0), "=r"(r1), "=r"(r2), "=r"(r3) : "r"(addr));
}

// ============================================================
// K1: row-normalize; write fp32 AND bf16 copies
// ============================================================
__global__ void k_normalize(const float* __restrict__ x) {
    int warp = (blockIdx.x * blockDim.x + threadIdx.x) >> 5;
    int lane = threadIdx.x & 31;
    if (warp >= BATCH * NTOK) return;
    const float4* row = (const float4*)(x + (size_t)warp * DIM);
    float4 v0 = row[lane * 2 + 0];
    float4 v1 = row[lane * 2 + 1];
    float s = v0.x * v0.x + v0.y * v0.y + v0.z * v0.z + v0.w * v0.w
            + v1.x * v1.x + v1.y * v1.y + v1.z * v1.z + v1.w * v1.w;
    #pragma unroll
    for (int o = 16; o; o >>= 1) s += __shfl_xor_sync(0xffffffffu, s, o);
    float inv = 1.0f / (sqrtf(s) + EPSV);
    v0.x *= inv; v0.y *= inv; v0.z *= inv; v0.w *= inv;
    v1.x *= inv; v1.y *= inv; v1.z *= inv; v1.w *= inv;
    float4* out = (float4*)(g_tn + (size_t)warp * DIM);
    out[lane * 2 + 0] = v0;
    out[lane * 2 + 1] = v1;
    __nv_bfloat162 h0 = __floats2bfloat162_rn(v0.x, v0.y);
    __nv_bfloat162 h1 = __floats2bfloat162_rn(v0.z, v0.w);
    __nv_bfloat162 h2 = __floats2bfloat162_rn(v1.x, v1.y);
    __nv_bfloat162 h3 = __floats2bfloat162_rn(v1.z, v1.w);
    uint4 pk;
    pk.x = *(uint32_t*)&h0; pk.y = *(uint32_t*)&h1;
    pk.z = *(uint32_t*)&h2; pk.w = *(uint32_t*)&h3;
    *(uint4*)(g_tnh + (size_t)warp * DIM + lane * 8) = pk;
}

// ============================================================
// K2: approx sim via bf16 mma.sync (m16n8k16), fp32 accum.
//     (unchanged R11: LDSM + double buffer)
// ============================================================
__global__ __launch_bounds__(256) void k_gemm_bf16() {
    __shared__ __nv_bfloat16 As[2][128][40];   // 20 KB
    __shared__ __nv_bfloat16 Bs[2][128][40];   // 20 KB

    const int b       = blockIdx.z;
    const int rowBase = blockIdx.y * 128;
    const int colBase = blockIdx.x * 128;
    const __nv_bfloat16* __restrict__ T = g_tnh + (size_t)b * NTOK * DIM;

    const int tid  = threadIdx.x;
    const int wid  = tid >> 5;
    const int lane = tid & 31;
    const int wm = (wid & 3) * 32;
    const int wn = (wid >> 2) * 64;
    const int g  = lane >> 2;
    const int c  = lane & 3;
    const int lrow = lane & 15;
    const int lcol = (lane >> 4) << 3;

    const int fr = tid >> 1;
    const int fk = (tid & 1) * 16;
    const __nv_bfloat16* gA = T + (size_t)(rowBase + fr) * DIM + fk;
    const __nv_bfloat16* gB = T + (size_t)(colBase + fr) * DIM + fk;

    float cf[2][8][4];
    #pragma unroll
    for (int mt = 0; mt < 2; mt++)
        #pragma unroll
        for (int nt = 0; nt < 8; nt++)
            #pragma unroll
            for (int e = 0; e < 4; e++) cf[mt][nt][e] = 0.f;

    uint4 pa0 = *(const uint4*)(gA);
    uint4 pa1 = *(const uint4*)(gA + 8);
    uint4 pb0 = *(const uint4*)(gB);
    uint4 pb1 = *(const uint4*)(gB + 8);
    *(uint4*)&As[0][fr][fk + 0] = pa0;
    *(uint4*)&As[0][fr][fk + 8] = pa1;
    *(uint4*)&Bs[0][fr][fk + 0] = pb0;
    *(uint4*)&Bs[0][fr][fk + 8] = pb1;
    __syncthreads();

    int p = 0;
    for (int k0 = 0; k0 < DIM; k0 += 32) {
        const bool hasNext = (k0 + 32 < DIM);
        if (hasNext) {
            pa0 = *(const uint4*)(gA + k0 + 32);
            pa1 = *(const uint4*)(gA + k0 + 32 + 8);
            pb0 = *(const uint4*)(gB + k0 + 32);
            pb1 = *(const uint4*)(gB + k0 + 32 + 8);
        }

        #pragma unroll
        for (int ks = 0; ks < 32; ks += 16) {
            uint32_t a[2][4];
            ldsm_x4(a[0][0], a[0][1], a[0][2], a[0][3], &As[p][wm +  0 + lrow][ks + lcol]);
            ldsm_x4(a[1][0], a[1][1], a[1][2], a[1][3], &As[p][wm + 16 + lrow][ks + lcol]);
            uint32_t bb[8][2];
            #pragma unroll
            for (int ntp = 0; ntp < 4; ntp++) {
                uint32_t t0, t1, t2, t3;
                ldsm_x4(t0, t1, t2, t3, &Bs[p][wn + ntp * 16 + lrow][ks + lcol]);
                bb[2 * ntp    ][0] = t0;
                bb[2 * ntp + 1][0] = t1;
                bb[2 * ntp    ][1] = t2;
                bb[2 * ntp + 1][1] = t3;
            }
            #pragma unroll
            for (int mt = 0; mt < 2; mt++)
                #pragma unroll
                for (int nt = 0; nt < 8; nt++) {
                    asm volatile(
                        "mma.sync.aligned.m16n8k16.row.col.f32.bf16.bf16.f32 "
                        "{%0,%1,%2,%3}, {%4,%5,%6,%7}, {%8,%9}, {%0,%1,%2,%3};"
                        : "+f"(cf[mt][nt][0]), "+f"(cf[mt][nt][1]),
                          "+f"(cf[mt][nt][2]), "+f"(cf[mt][nt][3])
                        : "r"(a[mt][0]), "r"(a[mt][1]), "r"(a[mt][2]), "r"(a[mt][3]),
                          "r"(bb[nt][0]), "r"(bb[nt][1]));
                }
        }

        if (hasNext) {
            int q = p ^ 1;
            *(uint4*)&As[q][fr][fk + 0] = pa0;
            *(uint4*)&As[q][fr][fk + 8] = pa1;
            *(uint4*)&Bs[q][fr][fk + 0] = pb0;
            *(uint4*)&Bs[q][fr][fk + 8] = pb1;
            __syncthreads();
            p = q;
        }
    }

    float* C = g_sim + (size_t)b * NTOK * NTOK;
    #pragma unroll
    for (int mt = 0; mt < 2; mt++) {
        #pragma unroll
        for (int nt = 0; nt < 8; nt++) {
            int r0 = rowBase + wm + mt * 16 + g;
            int cc = colBase + wn + nt * 8 + 2 * c;
            *(float2*)(C + (size_t)r0 * NTOK + cc)       = make_float2(cf[mt][nt][0], cf[mt][nt][1]);
            *(float2*)(C + (size_t)(r0 + 8) * NTOK + cc) = make_float2(cf[mt][nt][2], cf[mt][nt][3]);
        }
    }
}

// ============================================================
// K3: zero output (134 MB)
// ============================================================
__global__ void k_zero(float4* __restrict__ out, int n4) {
    int i      = blockIdx.x * blockDim.x + threadIdx.x;
    int stride = gridDim.x * blockDim.x;
    for (; i < n4; i += stride) out[i] = make_float4(0.f, 0.f, 0.f, 0.f);
}

// ============================================================
// K4: top-16 CANDIDATES per row (one warp/row).  <-- profiled
//     ALL 8 row-chunks loaded up-front (8 back-to-back LDG.128,
//     MLP=8), then branchy sorted-insert on registers + the
//     proven 16-round tournament.
// ============================================================
__global__ void k_topk16() {
    int gr   = (blockIdx.x * blockDim.x + threadIdx.x) >> 5;
    int lane = threadIdx.x & 31;
    if (gr >= BATCH * NTOK) return;
    int n = gr & (NTOK - 1);
    const float4* __restrict__ rowv = (const float4*)(g_sim + (size_t)gr * NTOK);

    // batched loads: 8 independent LDG.128 in flight
    float4 w[8];
    #pragma unroll
    for (int i = 0; i < 8; i++) w[i] = rowv[i * 32 + lane];

    float val[KNN];
    int   idx[KNN];
    #pragma unroll
    for (int i = 0; i < KNN; i++) { val[i] = -3.4e38f; idx[i] = -1; }

    #pragma unroll
    for (int i = 0; i < 8; i++) {
        int jb = i * 128 + lane * 4;
        float vv[4] = { w[i].x, w[i].y, w[i].z, w[i].w };
        #pragma unroll
        for (int q = 0; q < 4; q++) {
            int   j = jb + q;
            float v = (j == n) ? -3.4e38f : vv[q];    // mask self
            if (v > val[KNN - 1]) {
                val[KNN - 1] = v; idx[KNN - 1] = j;
                #pragma unroll
                for (int p = KNN - 1; p > 0; --p) {
                    if (val[p] > val[p - 1]) {
                        float tv = val[p]; val[p] = val[p - 1]; val[p - 1] = tv;
                        int   ti = idx[p]; idx[p] = idx[p - 1]; idx[p - 1] = ti;
                    }
                }
            }
        }
    }

    int ptr = 0;
    #pragma unroll
    for (int t = 0; t < NCAND; t++) {
        float hv = (ptr < KNN) ? val[ptr] : -3.4e38f;
        int   hj = (ptr < KNN) ? idx[ptr] : -1;
        float bv = hv; int bl = lane;
        #pragma unroll
        for (int off = 16; off; off >>= 1) {
            float ov = __shfl_down_sync(0xffffffffu, bv, off);
            int   ol = __shfl_down_sync(0xffffffffu, bl, off);
            if (ov > bv) { bv = ov; bl = ol; }
        }
        bl = __shfl_sync(0xffffffffu, bl, 0);
        int bj = __shfl_sync(0xffffffffu, hj, bl);
        if (lane == 0) g_cand[gr * NCAND + t] = bj;
        if (lane == bl) ptr++;
    }
}

// ============================================================
// K5: exact fp32 rescore — MLP version (R15).
// ============================================================
__global__ void k_rescore() {
    int gr   = (blockIdx.x * blockDim.x + threadIdx.x) >> 5;
    int lane = threadIdx.x & 31;
    if (gr >= BATCH * NTOK) return;
    int b = gr >> 10;
    const float* __restrict__ base = g_tn + ((size_t)b << 10) * DIM;
    const float* __restrict__ own  = base + (size_t)(gr & (NTOK - 1)) * DIM;

    int myc = g_cand[gr * NCAND + (lane & (NCAND - 1))];

    float4 o0 = ((const float4*)own)[lane * 2 + 0];
    float4 o1 = ((const float4*)own)[lane * 2 + 1];

    float p[NCAND];
    #pragma unroll
    for (int t0 = 0; t0 < NCAND; t0 += 4) {
        float4 c0[4], c1[4];
        #pragma unroll
        for (int u = 0; u < 4; u++) {
            int cj = __shfl_sync(0xffffffffu, myc, t0 + u);
            const float4* cv = (const float4*)(base + (size_t)cj * DIM);
            c0[u] = cv[lane * 2 + 0];
            c1[u] = cv[lane * 2 + 1];
        }
        #pragma unroll
        for (int u = 0; u < 4; u++) {
            p[t0 + u] = o0.x * c0[u].x + o0.y * c0[u].y + o0.z * c0[u].z + o0.w * c0[u].w
                      + o1.x * c1[u].x + o1.y * c1[u].y + o1.z * c1[u].z + o1.w * c1[u].w;
        }
    }

    #pragma unroll
    for (int t = 0; t < NCAND; t++)
        #pragma unroll
        for (int off = 16; off; off >>= 1)
            p[t] += __shfl_xor_sync(0xffffffffu, p[t], off);

    #pragma unroll
    for (int t = 0; t < NCAND; t++) {
        int rank = 0;
        #pragma unroll
        for (int t2 = 0; t2 < NCAND; t2++)
            if (t2 != t)
                rank += (p[t2] > p[t]) || (p[t2] == p[t] && t2 < t);
        if (lane == t && rank < KNN)
            g_topk[gr * KNN + rank] = myc;
    }
}

// ============================================================
// K6: mutual-kNN edge scatter (one thread per (row, t))
// ============================================================
__global__ void k_mutual(float* __restrict__ out) {
    int e = blockIdx.x * blockDim.x + threadIdx.x;
    if (e >= BATCH * NTOK * KNN) return;
    int gr = e >> 3;            // global row
    int t  = e & 7;
    int b  = gr >> 10;
    int n  = gr & (NTOK - 1);
    int j  = g_topk[gr * KNN + t];
    const int* tj = g_topk + ((b << 10) + j) * KNN;
    bool mutual = false;
    #pragma unroll
    for (int s = 0; s < KNN; s++) mutual |= (tj[s] == n);
    if (mutual)
        out[((size_t)b << 20) + ((size_t)n << 10) + (size_t)j] = 1.0f;
}

// ============================================================
extern "C" void kernel_launch(void* const* d_in, const int* in_sizes, int n_in,
                              void* d_out, int out_size) {
    const float* tokens = (const float*)d_in[0];
    float* out = (float*)d_out;

    // 1: normalize
    k_normalize<<<BATCH * NTOK / 8, 256>>>(tokens);

    // 2: bf16 MMA sim
    dim3 gg(8, 8, BATCH);
    k_gemm_bf16<<<gg, 256>>>();

    // 3: zero 134 MB output
    k_zero<<<4096, 256>>>((float4*)out, BATCH * NTOK * NTOK / 4);

    // 4: candidate top-16  <-- profiled launch
    k_topk16<<<BATCH * NTOK / 8, 256>>>();

    // 5: exact rescore, one warp per row
    k_rescore<<<BATCH * NTOK / 8, 256>>>();

    // 6: mutual edges
    k_mutual<<<(BATCH * NTOK * KNN + 255) / 256, 256>>>(out);
}

// round 17
// speedup vs baseline: 2.0942x; 2.0942x over previous
#include <cuda_runtime.h>
#include <cuda_bf16.h>
#include <cstdint>

#define BATCH 32
#define NTOK  1024
#define DIM   256
#define KNN   8
#define NCAND 16
#define EPSV  1e-8f

typedef unsigned long long u64;

// ---- scratch (static __device__ globals; no allocation allowed) ----
__device__ float         g_tn [(size_t)BATCH * NTOK * DIM];   // 32 MB fp32 (exact rescore)
__device__ __nv_bfloat16 g_tnh[(size_t)BATCH * NTOK * DIM];   // 16 MB bf16 (MMA filter)
__device__ float         g_sim[(size_t)BATCH * NTOK * NTOK];  // 134 MB approx sim
__device__ int           g_cand[BATCH * NTOK * NCAND];        // 2 MB candidates
__device__ int           g_topk[BATCH * NTOK * KNN];          // 1 MB exact top-8

__device__ __forceinline__ void ldsm_x4(uint32_t& r0, uint32_t& r1,
                                        uint32_t& r2, uint32_t& r3,
                                        const void* p) {
    uint32_t addr = (uint32_t)__cvta_generic_to_shared(p);
    asm volatile("ldmatrix.sync.aligned.m8n8.x4.shared.b16 {%0,%1,%2,%3}, [%4];"
                 : "=r"(r0), "=r"(r1), "=r"(r2), "=r"(r3) : "r"(addr));
}

// ============================================================
// K1: row-normalize; write fp32 AND bf16 copies
// ============================================================
__global__ void k_normalize(const float* __restrict__ x) {
    int warp = (blockIdx.x * blockDim.x + threadIdx.x) >> 5;
    int lane = threadIdx.x & 31;
    if (warp >= BATCH * NTOK) return;
    const float4* row = (const float4*)(x + (size_t)warp * DIM);
    float4 v0 = row[lane * 2 + 0];
    float4 v1 = row[lane * 2 + 1];
    float s = v0.x * v0.x + v0.y * v0.y + v0.z * v0.z + v0.w * v0.w
            + v1.x * v1.x + v1.y * v1.y + v1.z * v1.z + v1.w * v1.w;
    #pragma unroll
    for (int o = 16; o; o >>= 1) s += __shfl_xor_sync(0xffffffffu, s, o);
    float inv = 1.0f / (sqrtf(s) + EPSV);
    v0.x *= inv; v0.y *= inv; v0.z *= inv; v0.w *= inv;
    v1.x *= inv; v1.y *= inv; v1.z *= inv; v1.w *= inv;
    float4* out = (float4*)(g_tn + (size_t)warp * DIM);
    out[lane * 2 + 0] = v0;
    out[lane * 2 + 1] = v1;
    __nv_bfloat162 h0 = __floats2bfloat162_rn(v0.x, v0.y);
    __nv_bfloat162 h1 = __floats2bfloat162_rn(v0.z, v0.w);
    __nv_bfloat162 h2 = __floats2bfloat162_rn(v1.x, v1.y);
    __nv_bfloat162 h3 = __floats2bfloat162_rn(v1.z, v1.w);
    uint4 pk;
    pk.x = *(uint32_t*)&h0; pk.y = *(uint32_t*)&h1;
    pk.z = *(uint32_t*)&h2; pk.w = *(uint32_t*)&h3;
    *(uint4*)(g_tnh + (size_t)warp * DIM + lane * 8) = pk;
}

// ============================================================
// K2: approx sim via bf16 mma.sync (m16n8k16), fp32 accum.
//     (unchanged R11: LDSM + double buffer)
// ============================================================
__global__ __launch_bounds__(256) void k_gemm_bf16() {
    __shared__ __nv_bfloat16 As[2][128][40];   // 20 KB
    __shared__ __nv_bfloat16 Bs[2][128][40];   // 20 KB

    const int b       = blockIdx.z;
    const int rowBase = blockIdx.y * 128;
    const int colBase = blockIdx.x * 128;
    const __nv_bfloat16* __restrict__ T = g_tnh + (size_t)b * NTOK * DIM;

    const int tid  = threadIdx.x;
    const int wid  = tid >> 5;
    const int lane = tid & 31;
    const int wm = (wid & 3) * 32;
    const int wn = (wid >> 2) * 64;
    const int g  = lane >> 2;
    const int c  = lane & 3;
    const int lrow = lane & 15;
    const int lcol = (lane >> 4) << 3;

    const int fr = tid >> 1;
    const int fk = (tid & 1) * 16;
    const __nv_bfloat16* gA = T + (size_t)(rowBase + fr) * DIM + fk;
    const __nv_bfloat16* gB = T + (size_t)(colBase + fr) * DIM + fk;

    float cf[2][8][4];
    #pragma unroll
    for (int mt = 0; mt < 2; mt++)
        #pragma unroll
        for (int nt = 0; nt < 8; nt++)
            #pragma unroll
            for (int e = 0; e < 4; e++) cf[mt][nt][e] = 0.f;

    uint4 pa0 = *(const uint4*)(gA);
    uint4 pa1 = *(const uint4*)(gA + 8);
    uint4 pb0 = *(const uint4*)(gB);
    uint4 pb1 = *(const uint4*)(gB + 8);
    *(uint4*)&As[0][fr][fk + 0] = pa0;
    *(uint4*)&As[0][fr][fk + 8] = pa1;
    *(uint4*)&Bs[0][fr][fk + 0] = pb0;
    *(uint4*)&Bs[0][fr][fk + 8] = pb1;
    __syncthreads();

    int p = 0;
    for (int k0 = 0; k0 < DIM; k0 += 32) {
        const bool hasNext = (k0 + 32 < DIM);
        if (hasNext) {
            pa0 = *(const uint4*)(gA + k0 + 32);
            pa1 = *(const uint4*)(gA + k0 + 32 + 8);
            pb0 = *(const uint4*)(gB + k0 + 32);
            pb1 = *(const uint4*)(gB + k0 + 32 + 8);
        }

        #pragma unroll
        for (int ks = 0; ks < 32; ks += 16) {
            uint32_t a[2][4];
            ldsm_x4(a[0][0], a[0][1], a[0][2], a[0][3], &As[p][wm +  0 + lrow][ks + lcol]);
            ldsm_x4(a[1][0], a[1][1], a[1][2], a[1][3], &As[p][wm + 16 + lrow][ks + lcol]);
            uint32_t bb[8][2];
            #pragma unroll
            for (int ntp = 0; ntp < 4; ntp++) {
                uint32_t t0, t1, t2, t3;
                ldsm_x4(t0, t1, t2, t3, &Bs[p][wn + ntp * 16 + lrow][ks + lcol]);
                bb[2 * ntp    ][0] = t0;
                bb[2 * ntp + 1][0] = t1;
                bb[2 * ntp    ][1] = t2;
                bb[2 * ntp + 1][1] = t3;
            }
            #pragma unroll
            for (int mt = 0; mt < 2; mt++)
                #pragma unroll
                for (int nt = 0; nt < 8; nt++) {
                    asm volatile(
                        "mma.sync.aligned.m16n8k16.row.col.f32.bf16.bf16.f32 "
                        "{%0,%1,%2,%3}, {%4,%5,%6,%7}, {%8,%9}, {%0,%1,%2,%3};"
                        : "+f"(cf[mt][nt][0]), "+f"(cf[mt][nt][1]),
                          "+f"(cf[mt][nt][2]), "+f"(cf[mt][nt][3])
                        : "r"(a[mt][0]), "r"(a[mt][1]), "r"(a[mt][2]), "r"(a[mt][3]),
                          "r"(bb[nt][0]), "r"(bb[nt][1]));
                }
        }

        if (hasNext) {
            int q = p ^ 1;
            *(uint4*)&As[q][fr][fk + 0] = pa0;
            *(uint4*)&As[q][fr][fk + 8] = pa1;
            *(uint4*)&Bs[q][fr][fk + 0] = pb0;
            *(uint4*)&Bs[q][fr][fk + 8] = pb1;
            __syncthreads();
            p = q;
        }
    }

    float* C = g_sim + (size_t)b * NTOK * NTOK;
    #pragma unroll
    for (int mt = 0; mt < 2; mt++) {
        #pragma unroll
        for (int nt = 0; nt < 8; nt++) {
            int r0 = rowBase + wm + mt * 16 + g;
            int cc = colBase + wn + nt * 8 + 2 * c;
            *(float2*)(C + (size_t)r0 * NTOK + cc)       = make_float2(cf[mt][nt][0], cf[mt][nt][1]);
            *(float2*)(C + (size_t)(r0 + 8) * NTOK + cc) = make_float2(cf[mt][nt][2], cf[mt][nt][3]);
        }
    }
}

// ============================================================
// K3: zero output (134 MB)
// ============================================================
__global__ void k_zero(float4* __restrict__ out, int n4) {
    int i      = blockIdx.x * blockDim.x + threadIdx.x;
    int stride = gridDim.x * blockDim.x;
    for (; i < n4; i += stride) out[i] = make_float4(0.f, 0.f, 0.f, 0.f);
}

// ============================================================
// K4: top-16 CANDIDATES per row (one warp/row).  <-- profiled
//     R11 insert phase (static-index branchy sorted-8), but the
//     tournament uses SHIFT-DOWN extraction: head is always
//     val[0]/idx[0]; the winning lane shifts its list by one
//     (static indices, predicated) -> NO dynamic indexing
//     anywhere -> arrays stay in registers, no local memory.
// ============================================================
__global__ void k_topk16() {
    int gr   = (blockIdx.x * blockDim.x + threadIdx.x) >> 5;
    int lane = threadIdx.x & 31;
    if (gr >= BATCH * NTOK) return;
    int n = gr & (NTOK - 1);
    const float* __restrict__ row = g_sim + (size_t)gr * NTOK;

    float val[KNN];
    int   idx[KNN];
    #pragma unroll
    for (int i = 0; i < KNN; i++) { val[i] = -3.4e38f; idx[i] = -1; }

    #pragma unroll 4
    for (int i = 0; i < NTOK / 32; i++) {
        int j = lane + i * 32;
        float v = row[j];
        if (j == n) v = -3.4e38f;          // mask self
        if (v > val[KNN - 1]) {
            val[KNN - 1] = v; idx[KNN - 1] = j;
            #pragma unroll
            for (int p = KNN - 1; p > 0; --p) {
                if (val[p] > val[p - 1]) {
                    float tv = val[p]; val[p] = val[p - 1]; val[p - 1] = tv;
                    int   ti = idx[p]; idx[p] = idx[p - 1]; idx[p - 1] = ti;
                }
            }
        }
    }

    // 16-round tournament; head always at slot 0 (static access)
    #pragma unroll
    for (int t = 0; t < NCAND; t++) {
        float bv = val[0]; int bl = lane;
        #pragma unroll
        for (int off = 16; off; off >>= 1) {
            float ov = __shfl_down_sync(0xffffffffu, bv, off);
            int   ol = __shfl_down_sync(0xffffffffu, bl, off);
            if (ov > bv) { bv = ov; bl = ol; }
        }
        bl = __shfl_sync(0xffffffffu, bl, 0);            // winner lane
        int bj = __shfl_sync(0xffffffffu, idx[0], bl);   // winner's head idx
        if (lane == 0) g_cand[gr * NCAND + t] = bj;
        if (lane == bl) {                                // shift down (static)
            #pragma unroll
            for (int p = 0; p < KNN - 1; p++) {
                val[p] = val[p + 1];
                idx[p] = idx[p + 1];
            }
            val[KNN - 1] = -3.4e38f;
            idx[KNN - 1] = -1;
        }
    }
}

// ============================================================
// K5: exact fp32 rescore — MLP version (R15).
// ============================================================
__global__ void k_rescore() {
    int gr   = (blockIdx.x * blockDim.x + threadIdx.x) >> 5;
    int lane = threadIdx.x & 31;
    if (gr >= BATCH * NTOK) return;
    int b = gr >> 10;
    const float* __restrict__ base = g_tn + ((size_t)b << 10) * DIM;
    const float* __restrict__ own  = base + (size_t)(gr & (NTOK - 1)) * DIM;

    int myc = g_cand[gr * NCAND + (lane & (NCAND - 1))];

    float4 o0 = ((const float4*)own)[lane * 2 + 0];
    float4 o1 = ((const float4*)own)[lane * 2 + 1];

    float p[NCAND];
    #pragma unroll
    for (int t0 = 0; t0 < NCAND; t0 += 4) {
        float4 c0[4], c1[4];
        #pragma unroll
        for (int u = 0; u < 4; u++) {
            int cj = __shfl_sync(0xffffffffu, myc, t0 + u);
            const float4* cv = (const float4*)(base + (size_t)cj * DIM);
            c0[u] = cv[lane * 2 + 0];
            c1[u] = cv[lane * 2 + 1];
        }
        #pragma unroll
        for (int u = 0; u < 4; u++) {
            p[t0 + u] = o0.x * c0[u].x + o0.y * c0[u].y + o0.z * c0[u].z + o0.w * c0[u].w
                      + o1.x * c1[u].x + o1.y * c1[u].y + o1.z * c1[u].z + o1.w * c1[u].w;
        }
    }

    #pragma unroll
    for (int t = 0; t < NCAND; t++)
        #pragma unroll
        for (int off = 16; off; off >>= 1)
            p[t] += __shfl_xor_sync(0xffffffffu, p[t], off);

    #pragma unroll
    for (int t = 0; t < NCAND; t++) {
        int rank = 0;
        #pragma unroll
        for (int t2 = 0; t2 < NCAND; t2++)
            if (t2 != t)
                rank += (p[t2] > p[t]) || (p[t2] == p[t] && t2 < t);
        if (lane == t && rank < KNN)
            g_topk[gr * KNN + rank] = myc;
    }
}

// ============================================================
// K6: mutual-kNN edge scatter (one thread per (row, t))
// ============================================================
__global__ void k_mutual(float* __restrict__ out) {
    int e = blockIdx.x * blockDim.x + threadIdx.x;
    if (e >= BATCH * NTOK * KNN) return;
    int gr = e >> 3;            // global row
    int t  = e & 7;
    int b  = gr >> 10;
    int n  = gr & (NTOK - 1);
    int j  = g_topk[gr * KNN + t];
    const int* tj = g_topk + ((b << 10) + j) * KNN;
    bool mutual = false;
    #pragma unroll
    for (int s = 0; s < KNN; s++) mutual |= (tj[s] == n);
    if (mutual)
        out[((size_t)b << 20) + ((size_t)n << 10) + (size_t)j] = 1.0f;
}

// ============================================================
extern "C" void kernel_launch(void* const* d_in, const int* in_sizes, int n_in,
                              void* d_out, int out_size) {
    const float* tokens = (const float*)d_in[0];
    float* out = (float*)d_out;

    // 1: normalize
    k_normalize<<<BATCH * NTOK / 8, 256>>>(tokens);

    // 2: bf16 MMA sim
    dim3 gg(8, 8, BATCH);
    k_gemm_bf16<<<gg, 256>>>();

    // 3: zero 134 MB output
    k_zero<<<4096, 256>>>((float4*)out, BATCH * NTOK * NTOK / 4);

    // 4: candidate top-16  <-- profiled launch
    k_topk16<<<BATCH * NTOK / 8, 256>>>();

    // 5: exact rescore, one warp per row
    k_rescore<<<BATCH * NTOK / 8, 256>>>();

    // 6: mutual edges
    k_mutual<<<(BATCH * NTOK * KNN + 255) / 256, 256>>>(out);
}